// round 4
// baseline (speedup 1.0000x reference)
#include <cuda_runtime.h>
#include <cuda_bf16.h>
#include <math.h>

#define NPTS 400000
#define BATCH 4
#define HH 352
#define WW 1216
#define HW (HH*WW)          // 428032
#define MPIX (BATCH*HW)     // 1712128
#define CIN 64
#define CHID 16
#define COUT 64

// k_reduce geometry: NPTS*64 floats = NPTS*16 float4 = 6,400,000
#define NF4      (NPTS*16)
#define RED_GRID 1250
#define RED_BLK  256
#define RED_STRIDE (RED_GRID*RED_BLK)      // 320000
#define RED_ITERS  (NF4/RED_STRIDE)        // 20 exact
#define RED_CHUNK  10

typedef unsigned long long ull;

// ---- scratch (device globals: no allocation allowed) ----
__device__ int   g_winner[MPIX];             // per-pixel winning point index (or -1)
__device__ int   g_flat[NPTS];               // per-point flat pixel index
__device__ float g_feats[(size_t)NPTS*COUT]; // per-point MLP output (losers zeroed)
__device__ float g_sum[COUT];
__device__ float g_sq[COUT];
__device__ int   g_count;
__device__ float g_a[COUT], g_b[COUT], g_cst[COUT];

// ---- packed f32x2 helpers (FFMA2: ptxas never emits this; PTX-only) ----
__device__ __forceinline__ ull pack2(float lo, float hi) {
    ull r; asm("mov.b64 %0, {%1, %2};" : "=l"(r) : "f"(lo), "f"(hi)); return r;
}
__device__ __forceinline__ ull ffma2(ull a, ull b, ull c) {
    ull d; asm("fma.rn.f32x2 %0, %1, %2, %3;" : "=l"(d) : "l"(a), "l"(b), "l"(c)); return d;
}
__device__ __forceinline__ float2 unpack2(ull v) {
    float2 f; asm("mov.b64 {%0, %1}, %2;" : "=f"(f.x), "=f"(f.y) : "l"(v)); return f;
}

// ---------------------------------------------------------------------------
// K0: reset winner map and accumulators (runs every graph replay)
// ---------------------------------------------------------------------------
__global__ void k_init() {
    int idx = blockIdx.x * blockDim.x + threadIdx.x;   // 1672*256 = 428032 int4
    int4 mone = make_int4(-1, -1, -1, -1);
    ((int4*)g_winner)[idx] = mone;
    if (blockIdx.x == 0) {
        if (threadIdx.x < COUT) { g_sum[threadIdx.x] = 0.f; g_sq[threadIdx.x] = 0.f; }
        if (threadIdx.x == COUT) g_count = 0;
    }
}

// ---------------------------------------------------------------------------
// K1: pinhole projection + last-index-wins scatter arbitration.
// Projection matches XLA's FMA-contracted dot chain. (numerics: DO NOT TOUCH)
// ---------------------------------------------------------------------------
__global__ void k_project(const float* __restrict__ pos,
                          const int*   __restrict__ batch,
                          const float* __restrict__ cam) {
    int n = blockIdx.x * blockDim.x + threadIdx.x;
    if (n >= NPTS) return;
    float x = pos[3*n + 0];
    float y = pos[3*n + 1];
    float z = pos[3*n + 2];
    int b = batch[n];
    const float* K = cam + 9*b;
    float p0 = 0.f, p1 = 0.f, p2 = 0.f;
    p0 = __fmaf_rn(K[0], x, p0); p0 = __fmaf_rn(K[1], y, p0); p0 = __fmaf_rn(K[2], z, p0);
    p1 = __fmaf_rn(K[3], x, p1); p1 = __fmaf_rn(K[4], y, p1); p1 = __fmaf_rn(K[5], z, p1);
    p2 = __fmaf_rn(K[6], x, p2); p2 = __fmaf_rn(K[7], y, p2); p2 = __fmaf_rn(K[8], z, p2);
    float u = __fdiv_rn(p0, p2);
    float v = __fdiv_rn(p1, p2);
    int ui = (int)fminf(fmaxf(floorf(u), 0.f), (float)(WW - 1));
    int vi = (int)fminf(fmaxf(floorf(v), 0.f), (float)(HH - 1));
    int flat = b * HW + vi * WW + ui;
    g_flat[n] = flat;
    atomicMax(&g_winner[flat], n);
}

// ---------------------------------------------------------------------------
// K2: MLP 64 -> relu(16) -> 64 for winning points; losers write zeros.
//     Packed f32x2 FMAs: identical rn rounding per half (bit-exact vs scalar).
// ---------------------------------------------------------------------------
__global__ void k_mlp(const float* __restrict__ fin,
                      const float* __restrict__ W1, const float* __restrict__ b1,
                      const float* __restrict__ W2, const float* __restrict__ b2) {
    __shared__ __align__(16) float sW1[CIN*CHID];   // [i][j], j-pairs contiguous
    __shared__ __align__(16) float sW2[CHID*COUT];  // [j][c], c-pairs contiguous
    __shared__ __align__(16) float sb1[CHID];
    __shared__ __align__(16) float sb2[COUT];
    int t = threadIdx.x;
    for (int k = t; k < CIN*CHID;  k += blockDim.x) sW1[k] = W1[k];
    for (int k = t; k < CHID*COUT; k += blockDim.x) sW2[k] = W2[k];
    if (t < CHID) sb1[t] = b1[t];
    if (t < COUT) sb2[t] = b2[t];
    __syncthreads();

    int n = blockIdx.x * blockDim.x + t;
    bool valid = (n < NPTS);
    bool win = false;
    if (valid) win = (g_winner[g_flat[n]] == n);
    unsigned m = __ballot_sync(0xffffffffu, win);
    if ((t & 31) == 0 && m) atomicAdd(&g_count, __popc(m));
    if (!valid) return;

    float* dst = g_feats + (size_t)n * COUT;
    if (!win) {
        float4 zz = make_float4(0.f, 0.f, 0.f, 0.f);
        #pragma unroll
        for (int c = 0; c < COUT; c += 4) *(float4*)(dst + c) = zz;
        return;
    }

    // ---- layer 1: 64 -> 16, packed over j (8 x f32x2 accumulators) ----
    const ull* w1p = (const ull*)sW1;   // [i][8]
    const ull* b1p = (const ull*)sb1;   // [8]
    ull hp[8];
    #pragma unroll
    for (int p = 0; p < 8; p++) hp[p] = b1p[p];

    const float4* f4 = (const float4*)(fin + (size_t)n * CIN);
    #pragma unroll
    for (int i4 = 0; i4 < CIN/4; i4++) {
        float4 f = f4[i4];
        ull fx = pack2(f.x, f.x), fy = pack2(f.y, f.y);
        ull fz = pack2(f.z, f.z), fw = pack2(f.w, f.w);
        int i = i4 * 4;
        #pragma unroll
        for (int p = 0; p < 8; p++) hp[p] = ffma2(fx, w1p[(i+0)*8 + p], hp[p]);
        #pragma unroll
        for (int p = 0; p < 8; p++) hp[p] = ffma2(fy, w1p[(i+1)*8 + p], hp[p]);
        #pragma unroll
        for (int p = 0; p < 8; p++) hp[p] = ffma2(fz, w1p[(i+2)*8 + p], hp[p]);
        #pragma unroll
        for (int p = 0; p < 8; p++) hp[p] = ffma2(fw, w1p[(i+3)*8 + p], hp[p]);
    }

    // relu + broadcast-pack each hidden unit
    ull hh[CHID];
    #pragma unroll
    for (int p = 0; p < 8; p++) {
        float2 hv = unpack2(hp[p]);
        float h0 = fmaxf(hv.x, 0.f), h1 = fmaxf(hv.y, 0.f);
        hh[2*p+0] = pack2(h0, h0);
        hh[2*p+1] = pack2(h1, h1);
    }

    // ---- layer 2: 16 -> 64, 8 output channels (4 x f32x2) per sweep ----
    const ull* w2p = (const ull*)sW2;   // [j][32]
    const ull* b2p = (const ull*)sb2;   // [32]
    #pragma unroll
    for (int c8 = 0; c8 < 8; c8++) {
        ull o0 = b2p[c8*4+0], o1 = b2p[c8*4+1], o2 = b2p[c8*4+2], o3 = b2p[c8*4+3];
        #pragma unroll
        for (int j = 0; j < CHID; j++) {
            const ull* wrow = w2p + j*32 + c8*4;
            o0 = ffma2(hh[j], wrow[0], o0);
            o1 = ffma2(hh[j], wrow[1], o1);
            o2 = ffma2(hh[j], wrow[2], o2);
            o3 = ffma2(hh[j], wrow[3], o3);
        }
        ulonglong2 s0; s0.x = o0; s0.y = o1;
        ulonglong2 s1; s1.x = o2; s1.y = o3;
        ((ulonglong2*)dst)[c8*2+0] = s0;
        ((ulonglong2*)dst)[c8*2+1] = s1;
    }
}

// ---------------------------------------------------------------------------
// K2b: per-channel sum / sum-of-squares over g_feats (losers are zero).
// Software-pipelined: batches of 10 independent LDG.128 in named registers
// (MLP_eff ~10) so the stream is BW-bound, not latency-bound.
// ---------------------------------------------------------------------------
__global__ void k_reduce() {
    int tid  = blockIdx.x * RED_BLK + threadIdx.x;
    int lane = threadIdx.x & 31;
    int warp = threadIdx.x >> 5;
    int grp  = threadIdx.x & 15;        // channel group (channels 4*grp..4*grp+3)

    const float4* F = (const float4*)g_feats;
    float4 s = make_float4(0.f, 0.f, 0.f, 0.f);
    float4 q = make_float4(0.f, 0.f, 0.f, 0.f);

    float4 v[RED_CHUNK];
    #pragma unroll
    for (int b = 0; b < RED_ITERS / RED_CHUNK; b++) {
        #pragma unroll
        for (int k = 0; k < RED_CHUNK; k++)
            v[k] = F[tid + (b*RED_CHUNK + k) * RED_STRIDE];
        #pragma unroll
        for (int k = 0; k < RED_CHUNK; k++) {
            float4 f = v[k];
            s.x += f.x; s.y += f.y; s.z += f.z; s.w += f.w;
            q.x = fmaf(f.x, f.x, q.x); q.y = fmaf(f.y, f.y, q.y);
            q.z = fmaf(f.z, f.z, q.z); q.w = fmaf(f.w, f.w, q.w);
        }
    }

    // combine lane l with l^16 (same channel group)
    s.x += __shfl_xor_sync(0xffffffffu, s.x, 16);
    s.y += __shfl_xor_sync(0xffffffffu, s.y, 16);
    s.z += __shfl_xor_sync(0xffffffffu, s.z, 16);
    s.w += __shfl_xor_sync(0xffffffffu, s.w, 16);
    q.x += __shfl_xor_sync(0xffffffffu, q.x, 16);
    q.y += __shfl_xor_sync(0xffffffffu, q.y, 16);
    q.z += __shfl_xor_sync(0xffffffffu, q.z, 16);
    q.w += __shfl_xor_sync(0xffffffffu, q.w, 16);

    __shared__ float4 shS[8][16];
    __shared__ float4 shQ[8][16];
    if (lane < 16) { shS[warp][grp] = s; shQ[warp][grp] = q; }
    __syncthreads();

    if (threadIdx.x < 16) {
        int g = threadIdx.x;
        float4 ts = shS[0][g], tq = shQ[0][g];
        #pragma unroll
        for (int w = 1; w < 8; w++) {
            float4 a = shS[w][g], b = shQ[w][g];
            ts.x += a.x; ts.y += a.y; ts.z += a.z; ts.w += a.w;
            tq.x += b.x; tq.y += b.y; tq.z += b.z; tq.w += b.w;
        }
        atomicAdd(&g_sum[g*4+0], ts.x); atomicAdd(&g_sum[g*4+1], ts.y);
        atomicAdd(&g_sum[g*4+2], ts.z); atomicAdd(&g_sum[g*4+3], ts.w);
        atomicAdd(&g_sq[g*4+0], tq.x);  atomicAdd(&g_sq[g*4+1], tq.y);
        atomicAdd(&g_sq[g*4+2], tq.z);  atomicAdd(&g_sq[g*4+3], tq.w);
    }
}

// ---------------------------------------------------------------------------
// K3: finalize analytic BatchNorm affine: out = a_c * x + b_c ; const for empty
// ---------------------------------------------------------------------------
__global__ void k_stats(const float* __restrict__ zenc,
                        const float* __restrict__ gamma,
                        const float* __restrict__ beta) {
    int c = threadIdx.x;   // 64 threads
    double Mtot = (double)MPIX;
    double Kc = (double)g_count;
    double z  = (double)zenc[c];
    double S  = (double)g_sum[c];
    double Q  = (double)g_sq[c];
    double mean = ((Mtot - Kc) * z + S) / Mtot;
    double ex2  = ((Mtot - Kc) * z * z + Q) / Mtot;
    double var  = ex2 - mean * mean;
    double a = (double)gamma[c] / sqrt(var + 1e-5);
    float af = (float)a;
    float bf = beta[c] - (float)(mean * a);
    g_a[c] = af;
    g_b[c] = bf;
    g_cst[c] = (float)z * af + bf;
}

// ---------------------------------------------------------------------------
// K4: write output [B, C, H, W]. One thread = 4 consecutive pixels.
// float4 plane stores (streaming hint), int4 winner loads, branchless select.
// ---------------------------------------------------------------------------
__global__ void k_out(float* __restrict__ out) {
    __shared__ float sa[64], sb[64], sc[64];
    int t = threadIdx.x;
    if (t < 64) { sa[t] = g_a[t]; sb[t] = g_b[t]; sc[t] = g_cst[t]; }
    __syncthreads();

    int g = blockIdx.x * blockDim.x + t;     // MPIX/4 = 428032 = 1672*256 exactly
    int pix0 = g * 4;
    int bimg = pix0 / HW;                    // HW % 4 == 0 -> same batch for all 4
    int hw0 = pix0 - bimg * HW;

    int4 w4 = ((const int4*)g_winner)[g];
    bool win0 = w4.x >= 0, win1 = w4.y >= 0, win2 = w4.z >= 0, win3 = w4.w >= 0;
    const float4* r0 = (const float4*)g_feats + (size_t)(win0 ? w4.x : 0) * 16;
    const float4* r1 = (const float4*)g_feats + (size_t)(win1 ? w4.y : 0) * 16;
    const float4* r2 = (const float4*)g_feats + (size_t)(win2 ? w4.z : 0) * 16;
    const float4* r3 = (const float4*)g_feats + (size_t)(win3 ? w4.w : 0) * 16;

    float* o = out + (size_t)bimg * COUT * HW + hw0;

    #pragma unroll
    for (int c4 = 0; c4 < 16; c4++) {
        float4 f0 = r0[c4], f1 = r1[c4], f2 = r2[c4], f3 = r3[c4];
        const float* p0 = (const float*)&f0;
        const float* p1 = (const float*)&f1;
        const float* p2 = (const float*)&f2;
        const float* p3 = (const float*)&f3;
        #pragma unroll
        for (int cc = 0; cc < 4; cc++) {
            int c = c4 * 4 + cc;
            float a = sa[c], b = sb[c], z = sc[c];
            float4 v;
            v.x = win0 ? fmaf(p0[cc], a, b) : z;
            v.y = win1 ? fmaf(p1[cc], a, b) : z;
            v.z = win2 ? fmaf(p2[cc], a, b) : z;
            v.w = win3 ? fmaf(p3[cc], a, b) : z;
            __stcs((float4*)(o + (size_t)c * HW), v);
        }
    }
}

// ---------------------------------------------------------------------------
extern "C" void kernel_launch(void* const* d_in, const int* in_sizes, int n_in,
                              void* d_out, int out_size) {
    const float* pc_features = (const float*)d_in[0];
    const float* pc_pos      = (const float*)d_in[1];
    const int*   pc_batch    = (const int*)  d_in[2];
    const float* cam         = (const float*)d_in[3];
    const float* W1          = (const float*)d_in[4];
    const float* b1          = (const float*)d_in[5];
    const float* W2          = (const float*)d_in[6];
    const float* b2          = (const float*)d_in[7];
    const float* zenc        = (const float*)d_in[8];
    const float* gamma       = (const float*)d_in[9];
    const float* beta        = (const float*)d_in[10];
    float* out = (float*)d_out;

    k_init   <<<MPIX/4/256, 256>>>();                       // 1672 blocks
    k_project<<<(NPTS+255)/256, 256>>>(pc_pos, pc_batch, cam);
    k_mlp    <<<(NPTS+255)/256, 256>>>(pc_features, W1, b1, W2, b2);
    k_reduce <<<RED_GRID, RED_BLK>>>();
    k_stats  <<<1, 64>>>(zenc, gamma, beta);
    k_out    <<<MPIX/4/256, 256>>>(out);
}

// round 5
// speedup vs baseline: 1.0497x; 1.0497x over previous
#include <cuda_runtime.h>
#include <cuda_bf16.h>
#include <math.h>

#define NPTS 400000
#define BATCH 4
#define HH 352
#define WW 1216
#define HW (HH*WW)          // 428032
#define MPIX (BATCH*HW)     // 1712128
#define CIN 64
#define CHID 16
#define COUT 64

typedef unsigned long long ull;

// ---- scratch (device globals: no allocation allowed) ----
__device__ int   g_winner[MPIX];             // per-pixel winning point index (or -1)
__device__ int   g_flat[NPTS];               // per-point flat pixel index
__device__ float g_feats[(size_t)NPTS*COUT]; // per-point MLP output (winners only)
__device__ float g_sum[COUT];
__device__ float g_sq[COUT];
__device__ int   g_count;
__device__ float g_a[COUT], g_b[COUT], g_cst[COUT];

// ---- packed f32x2 helpers (FFMA2/FADD2: ptxas never emits; PTX-only) ----
__device__ __forceinline__ ull pack2(float lo, float hi) {
    ull r; asm("mov.b64 %0, {%1, %2};" : "=l"(r) : "f"(lo), "f"(hi)); return r;
}
__device__ __forceinline__ ull ffma2(ull a, ull b, ull c) {
    ull d; asm("fma.rn.f32x2 %0, %1, %2, %3;" : "=l"(d) : "l"(a), "l"(b), "l"(c)); return d;
}
__device__ __forceinline__ ull fmul2(ull a, ull b) {
    ull d; asm("mul.rn.f32x2 %0, %1, %2;" : "=l"(d) : "l"(a), "l"(b)); return d;
}
__device__ __forceinline__ ull fadd2(ull a, ull b) {
    ull d; asm("add.rn.f32x2 %0, %1, %2;" : "=l"(d) : "l"(a), "l"(b)); return d;
}
__device__ __forceinline__ float2 unpack2(ull v) {
    float2 f; asm("mov.b64 {%0, %1}, %2;" : "=f"(f.x), "=f"(f.y) : "l"(v)); return f;
}

// ---------------------------------------------------------------------------
// K0: reset winner map and accumulators (runs every graph replay)
// ---------------------------------------------------------------------------
__global__ void k_init() {
    int idx = blockIdx.x * blockDim.x + threadIdx.x;   // 1672*256 = 428032 int4
    int4 mone = make_int4(-1, -1, -1, -1);
    ((int4*)g_winner)[idx] = mone;
    if (blockIdx.x == 0) {
        if (threadIdx.x < COUT) { g_sum[threadIdx.x] = 0.f; g_sq[threadIdx.x] = 0.f; }
        if (threadIdx.x == COUT) g_count = 0;
    }
}

// ---------------------------------------------------------------------------
// K1: pinhole projection + last-index-wins scatter arbitration.
// Projection matches XLA's FMA-contracted dot chain. (numerics: DO NOT TOUCH)
// ---------------------------------------------------------------------------
__global__ void k_project(const float* __restrict__ pos,
                          const int*   __restrict__ batch,
                          const float* __restrict__ cam) {
    int n = blockIdx.x * blockDim.x + threadIdx.x;
    if (n >= NPTS) return;
    float x = pos[3*n + 0];
    float y = pos[3*n + 1];
    float z = pos[3*n + 2];
    int b = batch[n];
    const float* K = cam + 9*b;
    float p0 = 0.f, p1 = 0.f, p2 = 0.f;
    p0 = __fmaf_rn(K[0], x, p0); p0 = __fmaf_rn(K[1], y, p0); p0 = __fmaf_rn(K[2], z, p0);
    p1 = __fmaf_rn(K[3], x, p1); p1 = __fmaf_rn(K[4], y, p1); p1 = __fmaf_rn(K[5], z, p1);
    p2 = __fmaf_rn(K[6], x, p2); p2 = __fmaf_rn(K[7], y, p2); p2 = __fmaf_rn(K[8], z, p2);
    float u = __fdiv_rn(p0, p2);
    float v = __fdiv_rn(p1, p2);
    int ui = (int)fminf(fmaxf(floorf(u), 0.f), (float)(WW - 1));
    int vi = (int)fminf(fmaxf(floorf(v), 0.f), (float)(HH - 1));
    int flat = b * HW + vi * WW + ui;
    g_flat[n] = flat;
    atomicMax(&g_winner[flat], n);
}

// ---------------------------------------------------------------------------
// K2: fused MLP (64 -> relu(16) -> 64) + BN statistics reduction.
// Winners compute+store their row; losers contribute zeros to the stats.
// Per-warp 3-level f32x2 butterfly -> shared -> 128 global atomics per block.
// ---------------------------------------------------------------------------
__global__ void k_mlp(const float* __restrict__ fin,
                      const float* __restrict__ W1, const float* __restrict__ b1,
                      const float* __restrict__ W2, const float* __restrict__ b2) {
    __shared__ __align__(16) float sW1[CIN*CHID];   // [i][j]
    __shared__ __align__(16) float sW2[CHID*COUT];  // [j][c]
    __shared__ __align__(16) float sb1[CHID];
    __shared__ __align__(16) float sb2[COUT];
    __shared__ ull shS[8][4][32];   // [warp][lane0-3][chpair]  8KB
    __shared__ ull shQ[8][4][32];   // 8KB
    int t = threadIdx.x;
    int lane = t & 31, warp = t >> 5;
    for (int k = t; k < CIN*CHID;  k += blockDim.x) sW1[k] = W1[k];
    for (int k = t; k < CHID*COUT; k += blockDim.x) sW2[k] = W2[k];
    if (t < CHID) sb1[t] = b1[t];
    if (t < COUT) sb2[t] = b2[t];
    __syncthreads();

    int n = blockIdx.x * blockDim.x + t;
    bool valid = (n < NPTS);
    bool win = valid && (g_winner[g_flat[n]] == n);
    unsigned m = __ballot_sync(0xffffffffu, win);
    if (lane == 0 && m) atomicAdd(&g_count, __popc(m));

    ull ov[32];                    // 64 output channels as 32 f32x2
    #pragma unroll
    for (int k = 0; k < 32; k++) ov[k] = 0ull;   // 0ull == {0.f, 0.f}

    if (win) {
        // ---- layer 1: 64 -> 16 (8 packed accumulators) ----
        const ull* w1p = (const ull*)sW1;   // [i][8]
        const ull* b1p = (const ull*)sb1;
        ull hp[8];
        #pragma unroll
        for (int p = 0; p < 8; p++) hp[p] = b1p[p];

        const float4* f4 = (const float4*)(fin + (size_t)n * CIN);
        #pragma unroll
        for (int i4 = 0; i4 < CIN/4; i4++) {
            float4 f = f4[i4];
            ull fx = pack2(f.x, f.x), fy = pack2(f.y, f.y);
            ull fz = pack2(f.z, f.z), fw = pack2(f.w, f.w);
            int i = i4 * 4;
            #pragma unroll
            for (int p = 0; p < 8; p++) hp[p] = ffma2(fx, w1p[(i+0)*8 + p], hp[p]);
            #pragma unroll
            for (int p = 0; p < 8; p++) hp[p] = ffma2(fy, w1p[(i+1)*8 + p], hp[p]);
            #pragma unroll
            for (int p = 0; p < 8; p++) hp[p] = ffma2(fz, w1p[(i+2)*8 + p], hp[p]);
            #pragma unroll
            for (int p = 0; p < 8; p++) hp[p] = ffma2(fw, w1p[(i+3)*8 + p], hp[p]);
        }

        ull hh[CHID];
        #pragma unroll
        for (int p = 0; p < 8; p++) {
            float2 hv = unpack2(hp[p]);
            float h0 = fmaxf(hv.x, 0.f), h1 = fmaxf(hv.y, 0.f);
            hh[2*p+0] = pack2(h0, h0);
            hh[2*p+1] = pack2(h1, h1);
        }

        // ---- layer 2: 16 -> 64, into ov ----
        const ull* w2p = (const ull*)sW2;   // [j][32]
        const ull* b2p = (const ull*)sb2;
        #pragma unroll
        for (int c8 = 0; c8 < 8; c8++) {
            ull o0 = b2p[c8*4+0], o1 = b2p[c8*4+1], o2 = b2p[c8*4+2], o3 = b2p[c8*4+3];
            #pragma unroll
            for (int j = 0; j < CHID; j++) {
                const ull* wrow = w2p + j*32 + c8*4;
                o0 = ffma2(hh[j], wrow[0], o0);
                o1 = ffma2(hh[j], wrow[1], o1);
                o2 = ffma2(hh[j], wrow[2], o2);
                o3 = ffma2(hh[j], wrow[3], o3);
            }
            ov[c8*4+0] = o0; ov[c8*4+1] = o1; ov[c8*4+2] = o2; ov[c8*4+3] = o3;
        }

        // store row (winners only; loser rows never read downstream)
        float* dst = g_feats + (size_t)n * COUT;
        #pragma unroll
        for (int c8 = 0; c8 < 8; c8++) {
            ulonglong2 s0; s0.x = ov[c8*4+0]; s0.y = ov[c8*4+1];
            ulonglong2 s1; s1.x = ov[c8*4+2]; s1.y = ov[c8*4+3];
            ((ulonglong2*)dst)[c8*2+0] = s0;
            ((ulonglong2*)dst)[c8*2+1] = s1;
        }
    }

    // ---- fused BN stats: 3-level butterfly (lanes 0-3 hold partials) ----
    #pragma unroll
    for (int k = 0; k < 32; k++) {
        ull s = ov[k];
        ull q = fmul2(s, s);
        #pragma unroll
        for (int off = 16; off >= 4; off >>= 1) {
            s = fadd2(s, __shfl_xor_sync(0xffffffffu, s, off));
            q = fadd2(q, __shfl_xor_sync(0xffffffffu, q, off));
        }
        if (lane < 4) { shS[warp][lane][k] = s; shQ[warp][lane][k] = q; }
    }
    __syncthreads();

    if (t < 64) {
        int k = t & 31;               // channel pair
        bool isQ = (t >= 32);
        const ull (*sh)[4][32] = isQ ? shQ : shS;
        ull acc = 0ull;
        #pragma unroll
        for (int w = 0; w < 8; w++)
            #pragma unroll
            for (int l = 0; l < 4; l++)
                acc = fadd2(acc, sh[w][l][k]);
        float2 f = unpack2(acc);
        float* tgt = isQ ? g_sq : g_sum;
        atomicAdd(&tgt[2*k+0], f.x);
        atomicAdd(&tgt[2*k+1], f.y);
    }
}

// ---------------------------------------------------------------------------
// K3: finalize analytic BatchNorm affine: out = a_c * x + b_c ; const for empty
// ---------------------------------------------------------------------------
__global__ void k_stats(const float* __restrict__ zenc,
                        const float* __restrict__ gamma,
                        const float* __restrict__ beta) {
    int c = threadIdx.x;   // 64 threads
    double Mtot = (double)MPIX;
    double Kc = (double)g_count;
    double z  = (double)zenc[c];
    double S  = (double)g_sum[c];
    double Q  = (double)g_sq[c];
    double mean = ((Mtot - Kc) * z + S) / Mtot;
    double ex2  = ((Mtot - Kc) * z * z + Q) / Mtot;
    double var  = ex2 - mean * mean;
    double a = (double)gamma[c] / sqrt(var + 1e-5);
    float af = (float)a;
    float bf = beta[c] - (float)(mean * a);
    g_a[c] = af;
    g_b[c] = bf;
    g_cst[c] = (float)z * af + bf;
}

// ---------------------------------------------------------------------------
// K4: write output [B, C, H, W]. One thread = 4 consecutive pixels.
// float4 plane stores (streaming hint), int4 winner loads, branchless select.
// ---------------------------------------------------------------------------
__global__ void k_out(float* __restrict__ out) {
    __shared__ float sa[64], sb[64], sc[64];
    int t = threadIdx.x;
    if (t < 64) { sa[t] = g_a[t]; sb[t] = g_b[t]; sc[t] = g_cst[t]; }
    __syncthreads();

    int g = blockIdx.x * blockDim.x + t;     // MPIX/4 = 428032 = 1672*256 exactly
    int pix0 = g * 4;
    int bimg = pix0 / HW;                    // HW % 4 == 0 -> same batch for all 4
    int hw0 = pix0 - bimg * HW;

    int4 w4 = ((const int4*)g_winner)[g];
    bool win0 = w4.x >= 0, win1 = w4.y >= 0, win2 = w4.z >= 0, win3 = w4.w >= 0;
    const float4* r0 = (const float4*)g_feats + (size_t)(win0 ? w4.x : 0) * 16;
    const float4* r1 = (const float4*)g_feats + (size_t)(win1 ? w4.y : 0) * 16;
    const float4* r2 = (const float4*)g_feats + (size_t)(win2 ? w4.z : 0) * 16;
    const float4* r3 = (const float4*)g_feats + (size_t)(win3 ? w4.w : 0) * 16;

    float* o = out + (size_t)bimg * COUT * HW + hw0;

    #pragma unroll
    for (int c4 = 0; c4 < 16; c4++) {
        float4 f0 = r0[c4], f1 = r1[c4], f2 = r2[c4], f3 = r3[c4];
        const float* p0 = (const float*)&f0;
        const float* p1 = (const float*)&f1;
        const float* p2 = (const float*)&f2;
        const float* p3 = (const float*)&f3;
        #pragma unroll
        for (int cc = 0; cc < 4; cc++) {
            int c = c4 * 4 + cc;
            float a = sa[c], b = sb[c], z = sc[c];
            float4 v;
            v.x = win0 ? fmaf(p0[cc], a, b) : z;
            v.y = win1 ? fmaf(p1[cc], a, b) : z;
            v.z = win2 ? fmaf(p2[cc], a, b) : z;
            v.w = win3 ? fmaf(p3[cc], a, b) : z;
            __stcs((float4*)(o + (size_t)c * HW), v);
        }
    }
}

// ---------------------------------------------------------------------------
extern "C" void kernel_launch(void* const* d_in, const int* in_sizes, int n_in,
                              void* d_out, int out_size) {
    const float* pc_features = (const float*)d_in[0];
    const float* pc_pos      = (const float*)d_in[1];
    const int*   pc_batch    = (const int*)  d_in[2];
    const float* cam         = (const float*)d_in[3];
    const float* W1          = (const float*)d_in[4];
    const float* b1          = (const float*)d_in[5];
    const float* W2          = (const float*)d_in[6];
    const float* b2          = (const float*)d_in[7];
    const float* zenc        = (const float*)d_in[8];
    const float* gamma       = (const float*)d_in[9];
    const float* beta        = (const float*)d_in[10];
    float* out = (float*)d_out;

    k_init   <<<MPIX/4/256, 256>>>();                       // 1672 blocks
    k_project<<<(NPTS+255)/256, 256>>>(pc_pos, pc_batch, cam);
    k_mlp    <<<(NPTS+255)/256, 256>>>(pc_features, W1, b1, W2, b2);
    k_stats  <<<1, 64>>>(zenc, gamma, beta);
    k_out    <<<MPIX/4/256, 256>>>(out);
}